// round 14
// baseline (speedup 1.0000x reference)
#include <cuda_runtime.h>
#include <cuda_fp16.h>
#include <cstdint>

namespace {
constexpr int Tlen = 4096;
constexpr int IN   = 8;
constexpr int H    = 64;
constexpr int NB   = 4;
constexpr int NTHR = 512;   // warps 0-7: layer0 group, 8-15: layer1 group
constexpr int NBLK = 128;

using u32 = unsigned int;

constexpr int PH = 72;  // h ring row pitch (halves) = 144 B
constexpr int PX = 40;  // x ring row pitch (halves) = 80 B

#define BARSYNC(id, cnt) asm volatile("bar.sync %0, %1;" ::"r"(id), "r"(cnt) : "memory")
#define BARARR(id, cnt)  asm volatile("bar.arrive %0, %1;" ::"r"(id), "r"(cnt) : "memory")
// ids: 1=INT0, 2=INT1, 3+p=FULL[p], 5+p=FREE[p]

__device__ __forceinline__ float tanh_fast(float x) {
  float y;
  asm("tanh.approx.f32 %0, %1;" : "=f"(y) : "f"(x));
  return y;
}
__device__ __forceinline__ float sigmoid_fast(float x) {
  return fmaf(0.5f, tanh_fast(0.5f * x), 0.5f);
}
__device__ __forceinline__ u32 smem_u32(const void* p) {
  u32 a;
  asm("{ .reg .u64 t; cvta.to.shared.u64 t, %1; cvt.u32.u64 %0, t; }" : "=r"(a) : "l"(p));
  return a;
}
__device__ __forceinline__ void ldsm_x2(u32& r0, u32& r1, u32 addr) {
  asm volatile("ldmatrix.sync.aligned.m8n8.x2.shared.b16 {%0,%1}, [%2];"
               : "=r"(r0), "=r"(r1) : "r"(addr));
}
__device__ __forceinline__ void mma16816(float& c0, float& c1, float& c2, float& c3,
                                         const u32* a, u32 b0, u32 b1) {
  asm volatile(
      "mma.sync.aligned.m16n8k16.row.col.f32.f16.f16.f32 "
      "{%0,%1,%2,%3}, {%4,%5,%6,%7}, {%8,%9}, {%0,%1,%2,%3};"
      : "+f"(c0), "+f"(c1), "+f"(c2), "+f"(c3)
      : "r"(a[0]), "r"(a[1]), "r"(a[2]), "r"(a[3]), "r"(b0), "r"(b1));
}
__device__ __forceinline__ u32 pack2(float lo, float hi) {
  __half2 h = __floats2half2_rn(lo, hi);
  return *reinterpret_cast<u32*>(&h);
}
}  // namespace

__global__ __launch_bounds__(NTHR, 1) void lstm2_ws2_kernel(
    const float* __restrict__ x,
    const float* __restrict__ Wih0, const float* __restrict__ Whh0,
    const float* __restrict__ bih0, const float* __restrict__ bhh0,
    const float* __restrict__ Wih1, const float* __restrict__ Whh1,
    const float* __restrict__ bih1, const float* __restrict__ bhh1,
    const float* __restrict__ fcw, const float* __restrict__ fcb,
    float* __restrict__ out) {
  __shared__ __align__(16) unsigned short H0B[2][8 * PH];  // h0 ring [slot][n=batch][k=unit]
  __shared__ __align__(16) unsigned short H1B[2][8 * PH];  // h1 ring (L1-private)
  __shared__ __align__(16) unsigned short XB[2][8 * PX];   // x ring
  __shared__ float H1F[256];
  __shared__ float FCW[H];

  const int tid  = threadIdx.x;
  const int w    = tid >> 5;
  const int lane = tid & 31;
  const int b0   = blockIdx.x * NB;
  const int rq   = lane >> 2;
  const int cq   = (lane & 3) * 2;
  const bool g0  = (w < 8);
  const int wl   = g0 ? w : w - 8;
  const int glo  = rq & 1;       // low-gate index held by this lane
  const int uloc = rq >> 1;      // unit within tile (0..3)
  const int col  = cq + glo;     // batch column this lane finalizes
  const bool act = (lane & 3) < 2;  // cols 0..3 are real

  // zero rings
  for (int i = tid; i < 2 * 8 * PH; i += NTHR) { (&H0B[0][0])[i] = 0; (&H1B[0][0])[i] = 0; }
  for (int i = tid; i < 2 * 8 * PX; i += NTHR) (&XB[0][0])[i] = 0;
  if (tid < H) FCW[tid] = fcw[tid];
  if (g0 && wl == 7) {  // prestage x(0) into XB[0]
    XB[0][(lane >> 3) * PX + (lane & 7)] =
        __half_as_ushort(__float2half_rn(x[(long)(b0 + (lane >> 3)) * Tlen * IN + (lane & 7)]));
  }

  // per-lane pointwise units and biases (one per tile)
  int ju[2];
  float4 bq[2];
  {
    const float* bi = g0 ? bih0 : bih1;
    const float* bh = g0 ? bhh0 : bhh1;
#pragma unroll
    for (int tt = 0; tt < 2; ++tt) {
      ju[tt] = (wl * 2 + tt) * 4 + uloc;
      const int j = ju[tt];
      bq[tt] = make_float4(bi[j] + bh[j], bi[64 + j] + bh[64 + j],
                           bi[128 + j] + bh[128 + j], bi[192 + j] + bh[192 + j]);
    }
  }

  const u32 lrH = (lane & 7) * (PH * 2) + ((lane >> 3) & 1) * 16;
  const u32 lrX = (lane & 7) * (PX * 2) + ((lane >> 3) & 1) * 16;
  const u32 h0a[2] = {smem_u32(&H0B[0][0]) + lrH, smem_u32(&H0B[1][0]) + lrH};
  const u32 h1a[2] = {smem_u32(&H1B[0][0]) + lrH, smem_u32(&H1B[1][0]) + lrH};
  const u32 xba[2] = {smem_u32(&XB[0][0]) + lrX, smem_u32(&XB[1][0]) + lrX};

  __syncthreads();

  if (g0) {
    // ================= LAYER-0 GROUP =================
    // A rows permuted: tile row r -> gate (r&1)+2*(r>>3), unit T*4 + ((r&7)>>1)
    u32 A0[2][5][4];
#pragma unroll
    for (int tt = 0; tt < 2; ++tt) {
      const int T = wl * 2 + tt;
      auto wrow = [&](int r) { return ((r & 1) + 2 * (r >> 3)) * 64 + T * 4 + ((r & 7) >> 1); };
      auto ae = [&](int r, int k) -> float {
        int g = wrow(r);
        if (k < 64) return Whh0[g * H + k];
        if (k < 72) return Wih0[g * IN + (k - 64)];
        return 0.0f;
      };
#pragma unroll
      for (int kf = 0; kf < 5; ++kf) {
        const int c = kf * 16 + cq;
        A0[tt][kf][0] = pack2(ae(rq, c),         ae(rq, c + 1));
        A0[tt][kf][1] = pack2(ae(rq + 8, c),     ae(rq + 8, c + 1));
        A0[tt][kf][2] = pack2(ae(rq, c + 8),     ae(rq, c + 9));
        A0[tt][kf][3] = pack2(ae(rq + 8, c + 8), ae(rq + 8, c + 9));
      }
    }
    const bool isL = (wl == 7);
    const int xb_ = lane >> 3, xi = lane & 7;
    const long xbase = (long)(b0 + xb_) * Tlen * IN + xi;
    float xcur = isL ? __ldg(&x[xbase + IN]) : 0.0f;  // x(1)
    float cst[2] = {0.0f, 0.0f};

#pragma unroll 1
    for (int t = 0; t < Tlen; ++t) {
      const int cur = t & 1, rd = cur ^ 1;
      float xnext = 0.0f;
      if (isL && t + 2 < Tlen) xnext = __ldg(&x[xbase + (long)(t + 2) * IN]);

      u32 bf[5][2];
      ldsm_x2(bf[4][0], bf[4][1], xba[cur]);
#pragma unroll
      for (int kf = 0; kf < 4; ++kf) ldsm_x2(bf[kf][0], bf[kf][1], h0a[rd] + kf * 32);

      unsigned short hv[2];
#pragma unroll
      for (int tt = 0; tt < 2; ++tt) {
        float p0 = 0.f, p1 = 0.f, p2 = 0.f, p3 = 0.f;
        float q0 = 0.f, q1 = 0.f, q2 = 0.f, q3 = 0.f;
        mma16816(p0, p1, p2, p3, A0[tt][0], bf[0][0], bf[0][1]);
        mma16816(q0, q1, q2, q3, A0[tt][3], bf[3][0], bf[3][1]);
        mma16816(p0, p1, p2, p3, A0[tt][1], bf[1][0], bf[1][1]);
        mma16816(q0, q1, q2, q3, A0[tt][4], bf[4][0], bf[4][1]);
        mma16816(p0, p1, p2, p3, A0[tt][2], bf[2][0], bf[2][1]);
        const float d0 = p0 + q0, d1 = p1 + q1, d2 = p2 + q2, d3 = p3 + q3;
        // register exchange with lane^4: complete gate quad for (unit, col)
        float sa = glo ? d0 : d1;
        float sb = glo ? d2 : d3;
        sa = __shfl_xor_sync(0xffffffffu, sa, 4);
        sb = __shfl_xor_sync(0xffffffffu, sb, 4);
        const float gvi = glo ? sa : d0;
        const float gvf = glo ? d1 : sa;
        const float gvg = glo ? sb : d2;
        const float gvo = glo ? d3 : sb;
        if (act) {
          float gi = sigmoid_fast(gvi + bq[tt].x);
          float gf = sigmoid_fast(gvf + bq[tt].y);
          float gg = tanh_fast(gvg + bq[tt].z);
          float go = sigmoid_fast(gvo + bq[tt].w);
          cst[tt] = fmaf(gf, cst[tt], gi * gg);
          hv[tt] = __half_as_ushort(__float2half_rn(go * tanh_fast(cst[tt])));
        }
      }
      BARSYNC(5 + cur, 512);  // FREE: l1 done reading slot cur (from t-2)
      if (act) {
        H0B[cur][col * PH + ju[0]] = hv[0];
        H0B[cur][col * PH + ju[1]] = hv[1];
      }
      if (isL && t + 1 < Tlen) {
        XB[rd][xb_ * PX + xi] = __half_as_ushort(__float2half_rn(xcur));
        xcur = xnext;
      }
      BARSYNC(1, 256);        // INT0: h0(t)+x(t+1) visible in group
      BARARR(3 + cur, 512);   // FULL: signal l1
    }
  } else {
    // ================= LAYER-1 GROUP =================
    u32 A1[2][8][4];
#pragma unroll
    for (int tt = 0; tt < 2; ++tt) {
      const int T = wl * 2 + tt;
      auto wrow = [&](int r) { return ((r & 1) + 2 * (r >> 3)) * 64 + T * 4 + ((r & 7) >> 1); };
      auto ae = [&](int r, int k) -> float {
        int g = wrow(r);
        return (k < 64) ? Wih1[g * H + k] : Whh1[g * H + (k - 64)];
      };
#pragma unroll
      for (int kf = 0; kf < 8; ++kf) {
        const int c = kf * 16 + cq;
        A1[tt][kf][0] = pack2(ae(rq, c),         ae(rq, c + 1));
        A1[tt][kf][1] = pack2(ae(rq + 8, c),     ae(rq + 8, c + 1));
        A1[tt][kf][2] = pack2(ae(rq, c + 8),     ae(rq, c + 9));
        A1[tt][kf][3] = pack2(ae(rq + 8, c + 8), ae(rq + 8, c + 9));
      }
    }
    float cst[2] = {0.0f, 0.0f};
    BARARR(5, 512);  // prime FREE[0]
    BARARR(6, 512);  // prime FREE[1]

#pragma unroll 1
    for (int t = 0; t < Tlen; ++t) {
      const int cur = t & 1, rd = cur ^ 1;
      // ---- pre-barrier half: h1(t-1) contribution (own-group data) ----
      u32 hf[4][2];
#pragma unroll
      for (int kf = 0; kf < 4; ++kf) ldsm_x2(hf[kf][0], hf[kf][1], h1a[rd] + kf * 32);
      float S[2][4];
#pragma unroll
      for (int tt = 0; tt < 2; ++tt) {
        float s0 = 0.f, s1 = 0.f, s2 = 0.f, s3 = 0.f;
#pragma unroll
        for (int q = 0; q < 4; ++q)
          mma16816(s0, s1, s2, s3, A1[tt][q + 4], hf[q][0], hf[q][1]);
        S[tt][0] = s0; S[tt][1] = s1; S[tt][2] = s2; S[tt][3] = s3;
      }
      // ---- coupled half: h0(t) contribution ----
      BARSYNC(3 + cur, 512);  // FULL: h0(t) ready in slot cur
      u32 gfm[4][2];
#pragma unroll
      for (int kf = 0; kf < 4; ++kf) ldsm_x2(gfm[kf][0], gfm[kf][1], h0a[cur] + kf * 32);
      BARARR(5 + cur, 512);   // FREE: slot cur consumed

#pragma unroll
      for (int tt = 0; tt < 2; ++tt) {
        float r0 = 0.f, r1 = 0.f, r2 = 0.f, r3 = 0.f;
#pragma unroll
        for (int q = 0; q < 4; ++q)
          mma16816(r0, r1, r2, r3, A1[tt][q], gfm[q][0], gfm[q][1]);
        const float d0 = r0 + S[tt][0], d1 = r1 + S[tt][1];
        const float d2 = r2 + S[tt][2], d3 = r3 + S[tt][3];
        float sa = glo ? d0 : d1;
        float sb = glo ? d2 : d3;
        sa = __shfl_xor_sync(0xffffffffu, sa, 4);
        sb = __shfl_xor_sync(0xffffffffu, sb, 4);
        const float gvi = glo ? sa : d0;
        const float gvf = glo ? d1 : sa;
        const float gvg = glo ? sb : d2;
        const float gvo = glo ? d3 : sb;
        if (act) {
          float gi = sigmoid_fast(gvi + bq[tt].x);
          float gf = sigmoid_fast(gvf + bq[tt].y);
          float gg = tanh_fast(gvg + bq[tt].z);
          float go = sigmoid_fast(gvo + bq[tt].w);
          cst[tt] = fmaf(gf, cst[tt], gi * gg);
          float hvf = go * tanh_fast(cst[tt]);
          if (t + 1 < Tlen) {
            H1B[cur][col * PH + ju[tt]] = __half_as_ushort(__float2half_rn(hvf));
          } else {
            H1F[ju[tt] * 4 + col] = hvf;
          }
        }
      }
      BARSYNC(2, 256);        // INT1
    }
  }

  __syncthreads();
  if (tid < NB) {
    float acc = fcb[0];
#pragma unroll 16
    for (int j = 0; j < H; ++j) acc = fmaf(H1F[j * 4 + tid], FCW[j], acc);
    out[b0 + tid] = 1.0f / (1.0f + __expf(-acc));
  }
}

extern "C" void kernel_launch(void* const* d_in, const int* in_sizes, int n_in,
                              void* d_out, int out_size) {
  const float* x    = (const float*)d_in[0];
  const float* Wih0 = (const float*)d_in[1];
  const float* Whh0 = (const float*)d_in[2];
  const float* bih0 = (const float*)d_in[3];
  const float* bhh0 = (const float*)d_in[4];
  const float* Wih1 = (const float*)d_in[5];
  const float* Whh1 = (const float*)d_in[6];
  const float* bih1 = (const float*)d_in[7];
  const float* bhh1 = (const float*)d_in[8];
  const float* fcw  = (const float*)d_in[9];
  const float* fcb  = (const float*)d_in[10];
  float* out = (float*)d_out;

  lstm2_ws2_kernel<<<NBLK, NTHR>>>(x, Wih0, Whh0, bih0, bhh0, Wih1, Whh1,
                                   bih1, bhh1, fcw, fcb, out);
}

// round 15
// speedup vs baseline: 1.2612x; 1.2612x over previous
#include <cuda_runtime.h>
#include <cuda_fp16.h>
#include <cstdint>

namespace {
constexpr int Tlen = 4096;
constexpr int IN   = 8;
constexpr int H    = 64;
constexpr int NB   = 4;
constexpr int NTHR = 512;   // warps 0-7: layer0 group, 8-15: layer1 group
constexpr int NBLK = 128;

using u32 = unsigned int;

constexpr int PH = 72;  // h ring row pitch (halves) = 144 B
constexpr int PX = 40;  // x ring row pitch (halves) = 80 B

#define BARSYNC(id, cnt) asm volatile("bar.sync %0, %1;" ::"r"(id), "r"(cnt) : "memory")
#define BARARR(id, cnt)  asm volatile("bar.arrive %0, %1;" ::"r"(id), "r"(cnt) : "memory")
// ids: 1=INT0, 2=INT1, 3+p=FULL[p], 5+p=FREE[p]

__device__ __forceinline__ float tanh_fast(float x) {
  float y;
  asm("tanh.approx.f32 %0, %1;" : "=f"(y) : "f"(x));
  return y;
}
__device__ __forceinline__ float sigmoid_fast(float x) {
  return fmaf(0.5f, tanh_fast(0.5f * x), 0.5f);
}
__device__ __forceinline__ u32 smem_u32(const void* p) {
  u32 a;
  asm("{ .reg .u64 t; cvta.to.shared.u64 t, %1; cvt.u32.u64 %0, t; }" : "=r"(a) : "l"(p));
  return a;
}
__device__ __forceinline__ void ldsm_x2(u32& r0, u32& r1, u32 addr) {
  asm volatile("ldmatrix.sync.aligned.m8n8.x2.shared.b16 {%0,%1}, [%2];"
               : "=r"(r0), "=r"(r1) : "r"(addr));
}
__device__ __forceinline__ void ldsm_x4(u32& r0, u32& r1, u32& r2, u32& r3, u32 addr) {
  asm volatile("ldmatrix.sync.aligned.m8n8.x4.shared.b16 {%0,%1,%2,%3}, [%4];"
               : "=r"(r0), "=r"(r1), "=r"(r2), "=r"(r3) : "r"(addr));
}
__device__ __forceinline__ void mma16816(float& c0, float& c1, float& c2, float& c3,
                                         const u32* a, u32 b0, u32 b1) {
  asm volatile(
      "mma.sync.aligned.m16n8k16.row.col.f32.f16.f16.f32 "
      "{%0,%1,%2,%3}, {%4,%5,%6,%7}, {%8,%9}, {%0,%1,%2,%3};"
      : "+f"(c0), "+f"(c1), "+f"(c2), "+f"(c3)
      : "r"(a[0]), "r"(a[1]), "r"(a[2]), "r"(a[3]), "r"(b0), "r"(b1));
}
__device__ __forceinline__ u32 pack2(float lo, float hi) {
  __half2 h = __floats2half2_rn(lo, hi);
  return *reinterpret_cast<u32*>(&h);
}
}  // namespace

__global__ __launch_bounds__(NTHR, 1) void lstm2_ws3_kernel(
    const float* __restrict__ x,
    const float* __restrict__ Wih0, const float* __restrict__ Whh0,
    const float* __restrict__ bih0, const float* __restrict__ bhh0,
    const float* __restrict__ Wih1, const float* __restrict__ Whh1,
    const float* __restrict__ bih1, const float* __restrict__ bhh1,
    const float* __restrict__ fcw, const float* __restrict__ fcb,
    float* __restrict__ out) {
  __shared__ __align__(16) unsigned short H0B[2][8 * PH];  // h0 ring [slot][n=batch][k=unit]
  __shared__ __align__(16) unsigned short H1B[2][8 * PH];  // h1 ring (L1-private)
  __shared__ __align__(16) unsigned short XB[2][8 * PX];   // x ring
  __shared__ __align__(16) float GW[16][2][4][4][4];       // [warp][tile][u][col][gate]
  __shared__ float H1F[256];
  __shared__ float FCW[H];

  const int tid  = threadIdx.x;
  const int w    = tid >> 5;
  const int lane = tid & 31;
  const int b0   = blockIdx.x * NB;
  const int rq   = lane >> 2;
  const int cq   = (lane & 3) * 2;
  const bool g0  = (w < 8);
  const int wl   = g0 ? w : w - 8;

  // zero rings
  for (int i = tid; i < 2 * 8 * PH; i += NTHR) { (&H0B[0][0])[i] = 0; (&H1B[0][0])[i] = 0; }
  for (int i = tid; i < 2 * 8 * PX; i += NTHR) (&XB[0][0])[i] = 0;
  if (tid < H) FCW[tid] = fcw[tid];
  if (g0 && wl == 7) {  // prestage x(0) into XB[0]
    XB[0][(lane >> 3) * PX + (lane & 7)] =
        __half_as_ushort(__float2half_rn(x[(long)(b0 + (lane >> 3)) * Tlen * IN + (lane & 7)]));
  }

  // per-lane pointwise task: tile tt_, unit tu, batch tb  (layer = group)
  const int tt_ = lane >> 4, tu = (lane >> 2) & 3, tb = lane & 3;
  const int tj  = (wl * 2 + tt_) * 4 + tu;  // unit 0..63
  float4 bq;
  {
    const float* bi = g0 ? bih0 : bih1;
    const float* bh = g0 ? bhh0 : bhh1;
    bq = make_float4(bi[tj] + bh[tj], bi[64 + tj] + bh[64 + tj],
                     bi[128 + tj] + bh[128 + tj], bi[192 + tj] + bh[192 + tj]);
  }

  // x4 ldsm address: row = lane&7, matrix m = lane>>3 at +16B each
  const u32 lrH4 = (lane & 7) * (PH * 2) + (lane >> 3) * 16;
  const u32 lrX  = (lane & 7) * (PX * 2) + ((lane >> 3) & 1) * 16;
  const u32 h0q[2] = {smem_u32(&H0B[0][0]) + lrH4, smem_u32(&H0B[1][0]) + lrH4};
  const u32 h1q[2] = {smem_u32(&H1B[0][0]) + lrH4, smem_u32(&H1B[1][0]) + lrH4};
  const u32 xq[2]  = {smem_u32(&XB[0][0]) + lrX, smem_u32(&XB[1][0]) + lrX};

  __syncthreads();

  if (g0) {
    // ================= LAYER-0 GROUP =================
    u32 A0[2][5][4];
#pragma unroll
    for (int tt = 0; tt < 2; ++tt) {
      const int T = wl * 2 + tt;
      auto wrow = [&](int r) { return (r & 3) * 64 + T * 4 + (r >> 2); };
      auto ae = [&](int r, int k) -> float {
        int g = wrow(r);
        if (k < 64) return Whh0[g * H + k];
        if (k < 72) return Wih0[g * IN + (k - 64)];
        return 0.0f;
      };
#pragma unroll
      for (int kf = 0; kf < 5; ++kf) {
        const int c = kf * 16 + cq;
        A0[tt][kf][0] = pack2(ae(rq, c),         ae(rq, c + 1));
        A0[tt][kf][1] = pack2(ae(rq + 8, c),     ae(rq + 8, c + 1));
        A0[tt][kf][2] = pack2(ae(rq, c + 8),     ae(rq, c + 9));
        A0[tt][kf][3] = pack2(ae(rq + 8, c + 8), ae(rq + 8, c + 9));
      }
    }
    const bool isL = (wl == 7);
    const int xb_ = lane >> 3, xi = lane & 7;
    const long xbase = (long)(b0 + xb_) * Tlen * IN + xi;
    float xcur = isL ? __ldg(&x[xbase + IN]) : 0.0f;  // x(1)
    float cst = 0.0f;

#define L0_BODY(T, P, RP)                                                          \
  {                                                                                \
    float xnext = 0.0f;                                                            \
    if (isL && (T) + 2 < Tlen) xnext = __ldg(&x[xbase + (long)((T) + 2) * IN]);    \
    u32 f0, f1, f2, f3, f4, f5, f6, f7, fx0, fx1;                                  \
    ldsm_x4(f0, f1, f2, f3, h0q[RP]);                                              \
    ldsm_x4(f4, f5, f6, f7, h0q[RP] + 64);                                         \
    ldsm_x2(fx0, fx1, xq[P]);                                                      \
    _Pragma("unroll")                                                              \
    for (int tt = 0; tt < 2; ++tt) {                                               \
      float p0 = 0.f, p1 = 0.f, p2 = 0.f, p3 = 0.f;                                \
      float q0 = 0.f, q1 = 0.f, q2 = 0.f, q3 = 0.f;                                \
      mma16816(p0, p1, p2, p3, A0[tt][0], f0, f1);                                 \
      mma16816(q0, q1, q2, q3, A0[tt][3], f6, f7);                                 \
      mma16816(p0, p1, p2, p3, A0[tt][1], f2, f3);                                 \
      mma16816(q0, q1, q2, q3, A0[tt][4], fx0, fx1);                               \
      mma16816(p0, p1, p2, p3, A0[tt][2], f4, f5);                                 \
      if ((lane & 3) < 2) {                                                        \
        const int u = rq >> 2, g = rq & 3;                                         \
        GW[w][tt][u][cq][g]         = p0 + q0;                                     \
        GW[w][tt][u][cq + 1][g]     = p1 + q1;                                     \
        GW[w][tt][u + 2][cq][g]     = p2 + q2;                                     \
        GW[w][tt][u + 2][cq + 1][g] = p3 + q3;                                     \
      }                                                                            \
    }                                                                              \
    __syncwarp();                                                                  \
    const float4 gv = *reinterpret_cast<const float4*>(&GW[w][tt_][tu][tb][0]);    \
    BARSYNC(5 + (P), 512);                                                         \
    {                                                                              \
      float gi = sigmoid_fast(gv.x + bq.x);                                        \
      float gf = sigmoid_fast(gv.y + bq.y);                                        \
      float gg = tanh_fast(gv.z + bq.z);                                           \
      float go = sigmoid_fast(gv.w + bq.w);                                        \
      cst = fmaf(gf, cst, gi * gg);                                                \
      H0B[P][tb * PH + tj] = __half_as_ushort(__float2half_rn(go * tanh_fast(cst))); \
    }                                                                              \
    if (isL && (T) + 1 < Tlen) {                                                   \
      XB[RP][xb_ * PX + xi] = __half_as_ushort(__float2half_rn(xcur));             \
      xcur = xnext;                                                                \
    }                                                                              \
    BARSYNC(1, 256);                                                               \
    BARARR(3 + (P), 512);                                                          \
  }

#pragma unroll 1
    for (int t = 0; t < Tlen; t += 2) {
      L0_BODY(t, 0, 1)
      L0_BODY(t + 1, 1, 0)
    }
#undef L0_BODY
  } else {
    // ================= LAYER-1 GROUP =================
    u32 A1[2][8][4];
#pragma unroll
    for (int tt = 0; tt < 2; ++tt) {
      const int T = wl * 2 + tt;
      auto wrow = [&](int r) { return (r & 3) * 64 + T * 4 + (r >> 2); };
      auto ae = [&](int r, int k) -> float {
        int g = wrow(r);
        return (k < 64) ? Wih1[g * H + k] : Whh1[g * H + (k - 64)];
      };
#pragma unroll
      for (int kf = 0; kf < 8; ++kf) {
        const int c = kf * 16 + cq;
        A1[tt][kf][0] = pack2(ae(rq, c),         ae(rq, c + 1));
        A1[tt][kf][1] = pack2(ae(rq + 8, c),     ae(rq + 8, c + 1));
        A1[tt][kf][2] = pack2(ae(rq, c + 8),     ae(rq, c + 9));
        A1[tt][kf][3] = pack2(ae(rq + 8, c + 8), ae(rq + 8, c + 9));
      }
    }
    float cst = 0.0f;
    BARARR(5, 512);  // prime FREE[0]
    BARARR(6, 512);  // prime FREE[1]

#define L1_BODY(T, P, RP)                                                          \
  {                                                                                \
    u32 e0, e1, e2, e3, e4, e5, e6, e7;                                            \
    ldsm_x4(e0, e1, e2, e3, h1q[RP]);                                              \
    ldsm_x4(e4, e5, e6, e7, h1q[RP] + 64);                                         \
    float S[2][4];                                                                 \
    _Pragma("unroll")                                                              \
    for (int tt = 0; tt < 2; ++tt) {                                               \
      float s0 = 0.f, s1 = 0.f, s2 = 0.f, s3 = 0.f;                                \
      mma16816(s0, s1, s2, s3, A1[tt][4], e0, e1);                                 \
      mma16816(s0, s1, s2, s3, A1[tt][5], e2, e3);                                 \
      mma16816(s0, s1, s2, s3, A1[tt][6], e4, e5);                                 \
      mma16816(s0, s1, s2, s3, A1[tt][7], e6, e7);                                 \
      S[tt][0] = s0; S[tt][1] = s1; S[tt][2] = s2; S[tt][3] = s3;                  \
    }                                                                              \
    BARSYNC(3 + (P), 512);                                                         \
    u32 d0, d1, d2, d3, d4, d5, d6, d7;                                            \
    ldsm_x4(d0, d1, d2, d3, h0q[P]);                                               \
    ldsm_x4(d4, d5, d6, d7, h0q[P] + 64);                                          \
    BARARR(5 + (P), 512);                                                          \
    _Pragma("unroll")                                                              \
    for (int tt = 0; tt < 2; ++tt) {                                               \
      float r0 = 0.f, r1 = 0.f, r2 = 0.f, r3 = 0.f;                                \
      mma16816(r0, r1, r2, r3, A1[tt][0], d0, d1);                                 \
      mma16816(r0, r1, r2, r3, A1[tt][1], d2, d3);                                 \
      mma16816(r0, r1, r2, r3, A1[tt][2], d4, d5);                                 \
      mma16816(r0, r1, r2, r3, A1[tt][3], d6, d7);                                 \
      if ((lane & 3) < 2) {                                                        \
        const int u = rq >> 2, g = rq & 3;                                         \
        GW[w][tt][u][cq][g]         = r0 + S[tt][0];                               \
        GW[w][tt][u][cq + 1][g]     = r1 + S[tt][1];                               \
        GW[w][tt][u + 2][cq][g]     = r2 + S[tt][2];                               \
        GW[w][tt][u + 2][cq + 1][g] = r3 + S[tt][3];                               \
      }                                                                            \
    }                                                                              \
    __syncwarp();                                                                  \
    const float4 gv = *reinterpret_cast<const float4*>(&GW[w][tt_][tu][tb][0]);    \
    {                                                                              \
      float gi = sigmoid_fast(gv.x + bq.x);                                        \
      float gf = sigmoid_fast(gv.y + bq.y);                                        \
      float gg = tanh_fast(gv.z + bq.z);                                           \
      float go = sigmoid_fast(gv.w + bq.w);                                        \
      cst = fmaf(gf, cst, gi * gg);                                                \
      float hv = go * tanh_fast(cst);                                              \
      if ((T) + 1 < Tlen) {                                                        \
        H1B[P][tb * PH + tj] = __half_as_ushort(__float2half_rn(hv));              \
      } else {                                                                     \
        H1F[tj * 4 + tb] = hv;                                                     \
      }                                                                            \
    }                                                                              \
    BARSYNC(2, 256);                                                               \
  }

#pragma unroll 1
    for (int t = 0; t < Tlen; t += 2) {
      L1_BODY(t, 0, 1)
      L1_BODY(t + 1, 1, 0)
    }
#undef L1_BODY
  }

  __syncthreads();
  if (tid < NB) {
    float acc = fcb[0];
#pragma unroll 16
    for (int j = 0; j < H; ++j) acc = fmaf(H1F[j * 4 + tid], FCW[j], acc);
    out[b0 + tid] = 1.0f / (1.0f + __expf(-acc));
  }
}

extern "C" void kernel_launch(void* const* d_in, const int* in_sizes, int n_in,
                              void* d_out, int out_size) {
  const float* x    = (const float*)d_in[0];
  const float* Wih0 = (const float*)d_in[1];
  const float* Whh0 = (const float*)d_in[2];
  const float* bih0 = (const float*)d_in[3];
  const float* bhh0 = (const float*)d_in[4];
  const float* Wih1 = (const float*)d_in[5];
  const float* Whh1 = (const float*)d_in[6];
  const float* bih1 = (const float*)d_in[7];
  const float* bhh1 = (const float*)d_in[8];
  const float* fcw  = (const float*)d_in[9];
  const float* fcb  = (const float*)d_in[10];
  float* out = (float*)d_out;

  lstm2_ws3_kernel<<<NBLK, NTHR>>>(x, Wih0, Whh0, bih0, bhh0, Wih1, Whh1,
                                   bih1, bhh1, fcw, fcb, out);
}

// round 16
// speedup vs baseline: 1.2862x; 1.0199x over previous
#include <cuda_runtime.h>
#include <cuda_fp16.h>
#include <cstdint>

namespace {
constexpr int Tlen = 4096;
constexpr int IN   = 8;
constexpr int H    = 64;
constexpr int NB   = 4;
constexpr int NTHR = 512;   // warps 0-7: layer0 group, 8-15: layer1 group
constexpr int NBLK = 128;

using u32 = unsigned int;

constexpr int PH = 72;  // h ring row pitch (halves) = 144 B
constexpr int PX = 40;  // x ring row pitch (halves) = 80 B

#define BARSYNC(id, cnt) asm volatile("bar.sync %0, %1;" ::"r"(id), "r"(cnt) : "memory")
#define BARARR(id, cnt)  asm volatile("bar.arrive %0, %1;" ::"r"(id), "r"(cnt) : "memory")
// ids: 1=INT0, 2=INT1, 3+p=FULL[p] (p=0..3), 7+p=FREE[p]

__device__ __forceinline__ float tanh_fast(float x) {
  float y;
  asm("tanh.approx.f32 %0, %1;" : "=f"(y) : "f"(x));
  return y;
}
__device__ __forceinline__ float sigmoid_fast(float x) {
  return fmaf(0.5f, tanh_fast(0.5f * x), 0.5f);
}
__device__ __forceinline__ u32 smem_u32(const void* p) {
  u32 a;
  asm("{ .reg .u64 t; cvta.to.shared.u64 t, %1; cvt.u32.u64 %0, t; }" : "=r"(a) : "l"(p));
  return a;
}
__device__ __forceinline__ void ldsm_x2(u32& r0, u32& r1, u32 addr) {
  asm volatile("ldmatrix.sync.aligned.m8n8.x2.shared.b16 {%0,%1}, [%2];"
               : "=r"(r0), "=r"(r1) : "r"(addr));
}
__device__ __forceinline__ void ldsm_x4(u32& r0, u32& r1, u32& r2, u32& r3, u32 addr) {
  asm volatile("ldmatrix.sync.aligned.m8n8.x4.shared.b16 {%0,%1,%2,%3}, [%4];"
               : "=r"(r0), "=r"(r1), "=r"(r2), "=r"(r3) : "r"(addr));
}
__device__ __forceinline__ void mma16816(float& c0, float& c1, float& c2, float& c3,
                                         const u32* a, u32 b0, u32 b1) {
  asm volatile(
      "mma.sync.aligned.m16n8k16.row.col.f32.f16.f16.f32 "
      "{%0,%1,%2,%3}, {%4,%5,%6,%7}, {%8,%9}, {%0,%1,%2,%3};"
      : "+f"(c0), "+f"(c1), "+f"(c2), "+f"(c3)
      : "r"(a[0]), "r"(a[1]), "r"(a[2]), "r"(a[3]), "r"(b0), "r"(b1));
}
__device__ __forceinline__ u32 pack2(float lo, float hi) {
  __half2 h = __floats2half2_rn(lo, hi);
  return *reinterpret_cast<u32*>(&h);
}
}  // namespace

__global__ __launch_bounds__(NTHR, 1) void lstm2_ws4_kernel(
    const float* __restrict__ x,
    const float* __restrict__ Wih0, const float* __restrict__ Whh0,
    const float* __restrict__ bih0, const float* __restrict__ bhh0,
    const float* __restrict__ Wih1, const float* __restrict__ Whh1,
    const float* __restrict__ bih1, const float* __restrict__ bhh1,
    const float* __restrict__ fcw, const float* __restrict__ fcb,
    float* __restrict__ out) {
  __shared__ __align__(16) unsigned short H0B[4][8 * PH];  // h0 ring, depth 4
  __shared__ __align__(16) unsigned short H1B[2][8 * PH];  // h1 ring (L1-private)
  __shared__ __align__(16) unsigned short XB[4][8 * PX];   // x ring, depth 4
  __shared__ __align__(16) float GW[16][2][4][4][4];       // [warp][tile][u][col][gate]
  __shared__ float H1F[256];
  __shared__ float FCW[H];

  const int tid  = threadIdx.x;
  const int w    = tid >> 5;
  const int lane = tid & 31;
  const int b0   = blockIdx.x * NB;
  const int rq   = lane >> 2;
  const int cq   = (lane & 3) * 2;
  const bool g0  = (w < 8);
  const int wl   = g0 ? w : w - 8;

  // zero rings
  for (int i = tid; i < 4 * 8 * PH; i += NTHR) (&H0B[0][0])[i] = 0;
  for (int i = tid; i < 2 * 8 * PH; i += NTHR) (&H1B[0][0])[i] = 0;
  for (int i = tid; i < 4 * 8 * PX; i += NTHR) (&XB[0][0])[i] = 0;
  if (tid < H) FCW[tid] = fcw[tid];
  if (g0 && wl == 7) {  // prestage x(0) into XB[0]
    XB[0][(lane >> 3) * PX + (lane & 7)] =
        __half_as_ushort(__float2half_rn(x[(long)(b0 + (lane >> 3)) * Tlen * IN + (lane & 7)]));
  }

  // per-lane pointwise task: tile tt_, unit tu, batch tb  (layer = group)
  const int tt_ = lane >> 4, tu = (lane >> 2) & 3, tb = lane & 3;
  const int tj  = (wl * 2 + tt_) * 4 + tu;  // unit 0..63
  float4 bq;
  {
    const float* bi = g0 ? bih0 : bih1;
    const float* bh = g0 ? bhh0 : bhh1;
    bq = make_float4(bi[tj] + bh[tj], bi[64 + tj] + bh[64 + tj],
                     bi[128 + tj] + bh[128 + tj], bi[192 + tj] + bh[192 + tj]);
  }

  const u32 lrH4 = (lane & 7) * (PH * 2) + (lane >> 3) * 16;
  const u32 lrX  = (lane & 7) * (PX * 2) + ((lane >> 3) & 1) * 16;
  u32 h0q[4], xq[4];
#pragma unroll
  for (int p = 0; p < 4; ++p) {
    h0q[p] = smem_u32(&H0B[p][0]) + lrH4;
    xq[p]  = smem_u32(&XB[p][0]) + lrX;
  }
  const u32 h1q[2] = {smem_u32(&H1B[0][0]) + lrH4, smem_u32(&H1B[1][0]) + lrH4};

  __syncthreads();

  if (g0) {
    // ================= LAYER-0 GROUP =================
    u32 A0[2][5][4];
#pragma unroll
    for (int tt = 0; tt < 2; ++tt) {
      const int T = wl * 2 + tt;
      auto wrow = [&](int r) { return (r & 3) * 64 + T * 4 + (r >> 2); };
      auto ae = [&](int r, int k) -> float {
        int g = wrow(r);
        if (k < 64) return Whh0[g * H + k];
        if (k < 72) return Wih0[g * IN + (k - 64)];
        return 0.0f;
      };
#pragma unroll
      for (int kf = 0; kf < 5; ++kf) {
        const int c = kf * 16 + cq;
        A0[tt][kf][0] = pack2(ae(rq, c),         ae(rq, c + 1));
        A0[tt][kf][1] = pack2(ae(rq + 8, c),     ae(rq + 8, c + 1));
        A0[tt][kf][2] = pack2(ae(rq, c + 8),     ae(rq, c + 9));
        A0[tt][kf][3] = pack2(ae(rq + 8, c + 8), ae(rq + 8, c + 9));
      }
    }
    const bool isL = (wl == 7);
    const int xb_ = lane >> 3, xi = lane & 7;
    const long xbase = (long)(b0 + xb_) * Tlen * IN + xi;
    float xcur = isL ? __ldg(&x[xbase + IN]) : 0.0f;  // x(1)
    float cst = 0.0f;

#define L0_BODY(T, P, RP, WX)                                                      \
  {                                                                                \
    float xnext = 0.0f;                                                            \
    if (isL && (T) + 2 < Tlen) xnext = __ldg(&x[xbase + (long)((T) + 2) * IN]);    \
    u32 f0, f1, f2, f3, f4, f5, f6, f7, fx0, fx1;                                  \
    ldsm_x4(f0, f1, f2, f3, h0q[RP]);                                              \
    ldsm_x4(f4, f5, f6, f7, h0q[RP] + 64);                                         \
    ldsm_x2(fx0, fx1, xq[P]);                                                      \
    _Pragma("unroll")                                                              \
    for (int tt = 0; tt < 2; ++tt) {                                               \
      float p0 = 0.f, p1 = 0.f, p2 = 0.f, p3 = 0.f;                                \
      float q0 = 0.f, q1 = 0.f, q2 = 0.f, q3 = 0.f;                                \
      mma16816(p0, p1, p2, p3, A0[tt][0], f0, f1);                                 \
      mma16816(q0, q1, q2, q3, A0[tt][3], f6, f7);                                 \
      mma16816(p0, p1, p2, p3, A0[tt][1], f2, f3);                                 \
      mma16816(q0, q1, q2, q3, A0[tt][4], fx0, fx1);                               \
      mma16816(p0, p1, p2, p3, A0[tt][2], f4, f5);                                 \
      if ((lane & 3) < 2) {                                                        \
        const int u = rq >> 2, g = rq & 3;                                         \
        GW[w][tt][u][cq][g]         = p0 + q0;                                     \
        GW[w][tt][u][cq + 1][g]     = p1 + q1;                                     \
        GW[w][tt][u + 2][cq][g]     = p2 + q2;                                     \
        GW[w][tt][u + 2][cq + 1][g] = p3 + q3;                                     \
      }                                                                            \
    }                                                                              \
    __syncwarp();                                                                  \
    const float4 gv = *reinterpret_cast<const float4*>(&GW[w][tt_][tu][tb][0]);    \
    float gi = sigmoid_fast(gv.x + bq.x);                                          \
    float gf = sigmoid_fast(gv.y + bq.y);                                          \
    float gg = tanh_fast(gv.z + bq.z);                                             \
    float go = sigmoid_fast(gv.w + bq.w);                                          \
    cst = fmaf(gf, cst, gi * gg);                                                  \
    const unsigned short hvh = __half_as_ushort(__float2half_rn(go * tanh_fast(cst))); \
    BARSYNC(7 + (P), 512);  /* FREE[P]: l1 done with slot P (t-4) */               \
    H0B[P][tb * PH + tj] = hvh;                                                    \
    if (isL && (T) + 1 < Tlen) {                                                   \
      XB[WX][xb_ * PX + xi] = __half_as_ushort(__float2half_rn(xcur));             \
      xcur = xnext;                                                                \
    }                                                                              \
    BARSYNC(1, 256);        /* INT0 */                                             \
    BARARR(3 + (P), 512);   /* FULL[P] */                                          \
  }

#pragma unroll 1
    for (int t = 0; t < Tlen; t += 4) {
      L0_BODY(t,     0, 3, 1)
      L0_BODY(t + 1, 1, 0, 2)
      L0_BODY(t + 2, 2, 1, 3)
      L0_BODY(t + 3, 3, 2, 0)
    }
#undef L0_BODY
  } else {
    // ================= LAYER-1 GROUP =================
    u32 A1[2][8][4];
#pragma unroll
    for (int tt = 0; tt < 2; ++tt) {
      const int T = wl * 2 + tt;
      auto wrow = [&](int r) { return (r & 3) * 64 + T * 4 + (r >> 2); };
      auto ae = [&](int r, int k) -> float {
        int g = wrow(r);
        return (k < 64) ? Wih1[g * H + k] : Whh1[g * H + (k - 64)];
      };
#pragma unroll
      for (int kf = 0; kf < 8; ++kf) {
        const int c = kf * 16 + cq;
        A1[tt][kf][0] = pack2(ae(rq, c),         ae(rq, c + 1));
        A1[tt][kf][1] = pack2(ae(rq + 8, c),     ae(rq + 8, c + 1));
        A1[tt][kf][2] = pack2(ae(rq, c + 8),     ae(rq, c + 9));
        A1[tt][kf][3] = pack2(ae(rq + 8, c + 8), ae(rq + 8, c + 9));
      }
    }
    float cst = 0.0f;
    BARARR(7, 512);   // prime FREE[0..3]
    BARARR(8, 512);
    BARARR(9, 512);
    BARARR(10, 512);

#define L1_BODY(T, P, P2, RP2)                                                     \
  {                                                                                \
    u32 e0, e1, e2, e3, e4, e5, e6, e7;                                            \
    ldsm_x4(e0, e1, e2, e3, h1q[RP2]);                                             \
    ldsm_x4(e4, e5, e6, e7, h1q[RP2] + 64);                                        \
    float S[2][4];                                                                 \
    _Pragma("unroll")                                                              \
    for (int tt = 0; tt < 2; ++tt) {                                               \
      float sa0 = 0.f, sa1 = 0.f, sa2 = 0.f, sa3 = 0.f;                            \
      float sb0 = 0.f, sb1 = 0.f, sb2 = 0.f, sb3 = 0.f;                            \
      mma16816(sa0, sa1, sa2, sa3, A1[tt][4], e0, e1);                             \
      mma16816(sb0, sb1, sb2, sb3, A1[tt][6], e4, e5);                             \
      mma16816(sa0, sa1, sa2, sa3, A1[tt][5], e2, e3);                             \
      mma16816(sb0, sb1, sb2, sb3, A1[tt][7], e6, e7);                             \
      S[tt][0] = sa0 + sb0; S[tt][1] = sa1 + sb1;                                  \
      S[tt][2] = sa2 + sb2; S[tt][3] = sa3 + sb3;                                  \
    }                                                                              \
    BARSYNC(3 + (P), 512);  /* FULL[P]: h0(T) ready */                             \
    u32 d0, d1, d2, d3, d4, d5, d6, d7;                                            \
    ldsm_x4(d0, d1, d2, d3, h0q[P]);                                               \
    ldsm_x4(d4, d5, d6, d7, h0q[P] + 64);                                          \
    BARARR(7 + (P), 512);   /* FREE[P] */                                          \
    _Pragma("unroll")                                                              \
    for (int tt = 0; tt < 2; ++tt) {                                               \
      float ra0 = 0.f, ra1 = 0.f, ra2 = 0.f, ra3 = 0.f;                            \
      float rb0 = 0.f, rb1 = 0.f, rb2 = 0.f, rb3 = 0.f;                            \
      mma16816(ra0, ra1, ra2, ra3, A1[tt][0], d0, d1);                             \
      mma16816(rb0, rb1, rb2, rb3, A1[tt][2], d4, d5);                             \
      mma16816(ra0, ra1, ra2, ra3, A1[tt][1], d2, d3);                             \
      mma16816(rb0, rb1, rb2, rb3, A1[tt][3], d6, d7);                             \
      if ((lane & 3) < 2) {                                                        \
        const int u = rq >> 2, g = rq & 3;                                         \
        GW[w][tt][u][cq][g]         = (ra0 + rb0) + S[tt][0];                      \
        GW[w][tt][u][cq + 1][g]     = (ra1 + rb1) + S[tt][1];                      \
        GW[w][tt][u + 2][cq][g]     = (ra2 + rb2) + S[tt][2];                      \
        GW[w][tt][u + 2][cq + 1][g] = (ra3 + rb3) + S[tt][3];                      \
      }                                                                            \
    }                                                                              \
    __syncwarp();                                                                  \
    const float4 gv = *reinterpret_cast<const float4*>(&GW[w][tt_][tu][tb][0]);    \
    {                                                                              \
      float gi = sigmoid_fast(gv.x + bq.x);                                        \
      float gf = sigmoid_fast(gv.y + bq.y);                                        \
      float gg = tanh_fast(gv.z + bq.z);                                           \
      float go = sigmoid_fast(gv.w + bq.w);                                        \
      cst = fmaf(gf, cst, gi * gg);                                                \
      float hv = go * tanh_fast(cst);                                              \
      if ((T) + 1 < Tlen) {                                                        \
        H1B[P2][tb * PH + tj] = __half_as_ushort(__float2half_rn(hv));             \
      } else {                                                                     \
        H1F[tj * 4 + tb] = hv;                                                     \
      }                                                                            \
    }                                                                              \
    BARSYNC(2, 256);        /* INT1 */                                             \
  }

#pragma unroll 1
    for (int t = 0; t < Tlen; t += 4) {
      L1_BODY(t,     0, 0, 1)
      L1_BODY(t + 1, 1, 1, 0)
      L1_BODY(t + 2, 2, 0, 1)
      L1_BODY(t + 3, 3, 1, 0)
    }
#undef L1_BODY
  }

  __syncthreads();
  if (tid < NB) {
    float acc = fcb[0];
#pragma unroll 16
    for (int j = 0; j < H; ++j) acc = fmaf(H1F[j * 4 + tid], FCW[j], acc);
    out[b0 + tid] = 1.0f / (1.0f + __expf(-acc));
  }
}

extern "C" void kernel_launch(void* const* d_in, const int* in_sizes, int n_in,
                              void* d_out, int out_size) {
  const float* x    = (const float*)d_in[0];
  const float* Wih0 = (const float*)d_in[1];
  const float* Whh0 = (const float*)d_in[2];
  const float* bih0 = (const float*)d_in[3];
  const float* bhh0 = (const float*)d_in[4];
  const float* Wih1 = (const float*)d_in[5];
  const float* Whh1 = (const float*)d_in[6];
  const float* bih1 = (const float*)d_in[7];
  const float* bhh1 = (const float*)d_in[8];
  const float* fcw  = (const float*)d_in[9];
  const float* fcb  = (const float*)d_in[10];
  float* out = (float*)d_out;

  lstm2_ws4_kernel<<<NBLK, NTHR>>>(x, Wih0, Whh0, bih0, bhh0, Wih1, Whh1,
                                   bih1, bhh1, fcw, fcb, out);
}